// round 5
// baseline (speedup 1.0000x reference)
#include <cuda_runtime.h>
#include <cstdint>
#include <cstddef>

// Problem constants
#define Bn 4
#define Cn 128
#define Hn 128
#define Wn 256
#define Dn 81
#define HWn (Hn * Wn)
#define TH 2        // output rows per block
#define TWt 128     // output cols per block
#define NTHREADS 192
#define CPS 2       // channels per pipeline stage
#define NSTG (Cn / CPS)
#define NBUF 3      // triple-buffered stages

// pack two ADJACENT float regs into an f32x2 operand
__device__ __forceinline__ double pkd(float a, float b) {
    double d;
    asm("mov.b64 %0, {%1, %2};" : "=d"(d) : "f"(a), "f"(b));
    return d;
}
__device__ __forceinline__ void fma2(double &d, double a, double b) {
    asm("fma.rn.f32x2 %0, %1, %2, %0;" : "+d"(d) : "d"(a), "d"(b));
}
// cp.async 16B; src_sz=0 -> writes 16 zero bytes (halo fill)
__device__ __forceinline__ void cp16(void* dst_smem, const void* src, bool ok) {
    unsigned dst = (unsigned)__cvta_generic_to_shared(dst_smem);
    int sz = ok ? 16 : 0;
    asm volatile("cp.async.ca.shared.global [%0], [%1], 16, %2;" :: "r"(dst), "l"(src), "r"(sz));
}

__global__ void __launch_bounds__(NTHREADS, 2)
cost_volume_kernel(const float* __restrict__ x1,
                   const float* __restrict__ x2,
                   float* __restrict__ out)
{
    // x2 tile rows h0-4 .. h0+5 (10) x 136 cols; triple buffered, 2 ch/stage
    __shared__ __align__(16) float x2s[NBUF][CPS][10][136];   // 32640 B
    __shared__ __align__(16) float x1s[NBUF][CPS][TH][TWt];   //  6144 B

    const int tid  = threadIdx.x;
    const int lane = tid & 31;
    const int warp = tid >> 5;     // 0..5
    const int g    = warp >> 1;    // di-group 0..2
    const int row  = warp & 1;     // output row in tile (0..1)

    const int w0 = blockIdx.x * TWt;
    const int h0 = blockIdx.y * TH;
    const int bb = blockIdx.z;

    // even-dj accumulators: [rr][ej][lo/hi] as f32x2; odd-dj scalars
    double acc_e[30];
    float  acc_o[48];
#pragma unroll
    for (int i = 0; i < 30; ++i) acc_e[i] = 0.0;
#pragma unroll
    for (int i = 0; i < 48; ++i) acc_o[i] = 0.0f;

    // ---------- hoisted loader state (channel-invariant), 3 chunk slots ----
    // chunks: x2 ids [0,340) = 10 rows x 34; x1 ids [340,404) = 2 rows x 32
    unsigned  so[3];
    long long gofs[3];
    bool okf[3], act[3], isx1[3];
#pragma unroll
    for (int s = 0; s < 3; ++s) {
        int id = tid + s * NTHREADS;
        act[s] = false; okf[s] = false; isx1[s] = false; so[s] = 0; gofs[s] = 0;
        if (id < 340) {
            int rw = id / 34, c4 = id - rw * 34;
            int hs = h0 - 4 + rw, ws = w0 - 4 + c4 * 4;
            okf[s] = ((unsigned)hs < (unsigned)Hn) && ((unsigned)ws < (unsigned)Wn);
            gofs[s] = okf[s] ? (long long)(hs * Wn + ws) * 4 : 0;
            so[s] = (unsigned)(rw * 136 + c4 * 4) * 4;
            act[s] = true;
        } else if (id < 404) {
            int j = id - 340;
            int rw = j >> 5, c4 = j & 31;
            okf[s] = true; isx1[s] = true;
            gofs[s] = (long long)((h0 + rw) * Wn + w0 + c4 * 4) * 4;
            so[s] = (unsigned)(rw * TWt + c4 * 4) * 4;
            act[s] = true;
        }
    }
    const char* gp[3];
#pragma unroll
    for (int s = 0; s < 3; ++s)
        gp[s] = (const char*)((isx1[s] ? x1 : x2) + (size_t)bb * Cn * HWn) + gofs[s];

    const unsigned rbase = (unsigned)(row + 3 * g) * 136u * 4u + (unsigned)lane * 16u;

    auto load_ch = [&](int buf, int slot) {
#pragma unroll
        for (int s = 0; s < 3; ++s) {
            if (act[s]) {
                char* dst = (isx1[s] ? (char*)&x1s[buf][slot][0][0]
                                     : (char*)&x2s[buf][slot][0][0]) + so[s];
                cp16(dst, gp[s], okf[s]);
                gp[s] += (size_t)HWn * 4;
            }
        }
    };

    // prologue: stages 0 and 1
    load_ch(0, 0); load_ch(0, 1);
    asm volatile("cp.async.commit_group;");
    load_ch(1, 0); load_ch(1, 1);
    asm volatile("cp.async.commit_group;");

    int buf = 0, pfb = 2;
#pragma unroll 1
    for (int t = 0; t < NSTG; ++t) {
        if (t < NSTG - 1) asm volatile("cp.async.wait_group 1;");
        else              asm volatile("cp.async.wait_group 0;");
        __syncthreads();   // single barrier: data-ready + prior-reads-done

        if (t + 2 < NSTG) {
            load_ch(pfb, 0); load_ch(pfb, 1);
            asm volatile("cp.async.commit_group;");
        }

#pragma unroll
        for (int slot = 0; slot < CPS; ++slot) {
            const float4* xr = reinterpret_cast<const float4*>(&x1s[buf][slot][row][0]);
            float4 xv = xr[lane];
            float xs[4] = {xv.x, xv.y, xv.z, xv.w};
            double xlo = pkd(xv.x, xv.y);
            double xhi = pkd(xv.z, xv.w);

            const char* base = (const char*)&x2s[buf][slot][0][0] + rbase;
#pragma unroll
            for (int rr = 0; rr < 3; ++rr) {
                const float4* rp = reinterpret_cast<const float4*>(base + rr * (136 * 4));
                float4 q0 = rp[0], q1 = rp[1], q2 = rp[2];
                float v[12] = {q0.x, q0.y, q0.z, q0.w,
                               q1.x, q1.y, q1.z, q1.w,
                               q2.x, q2.y, q2.z, q2.w};
#pragma unroll
                for (int e = 0; e < 5; ++e) {
                    const int dj = 2 * e;
                    fma2(acc_e[(rr * 5 + e) * 2 + 0], xlo, pkd(v[dj],     v[dj + 1]));
                    fma2(acc_e[(rr * 5 + e) * 2 + 1], xhi, pkd(v[dj + 2], v[dj + 3]));
                }
#pragma unroll
                for (int o = 0; o < 4; ++o) {
                    const int dj = 2 * o + 1;
#pragma unroll
                    for (int p = 0; p < 4; ++p)
                        acc_o[(rr * 4 + o) * 4 + p] =
                            fmaf(xs[p], v[dj + p], acc_o[(rr * 4 + o) * 4 + p]);
                }
            }
        }
        buf = (buf == NBUF - 1) ? 0 : buf + 1;
        pfb = (pfb == NBUF - 1) ? 0 : pfb + 1;
    }

    // ---------- epilogue: scale + scatter ----------
    const float inv = 1.0f / 81.0f;
    const int h = h0 + row;
    const int di0 = 3 * g - 4;
#pragma unroll
    for (int rr = 0; rr < 3; ++rr) {
#pragma unroll
        for (int e = 0; e < 5; ++e) {
            const int djv = 2 * e - 4;
            const int tt = 9 * (di0 + rr) + djv;
            const int k = (81 - tt) % 81;
            double alo = acc_e[(rr * 5 + e) * 2 + 0];
            double ahi = acc_e[(rr * 5 + e) * 2 + 1];
            float4 o;
            o.x = __int_as_float(__double2loint(alo)) * inv;
            o.y = __int_as_float(__double2hiint(alo)) * inv;
            o.z = __int_as_float(__double2loint(ahi)) * inv;
            o.w = __int_as_float(__double2hiint(ahi)) * inv;
            float* dst = out + (((size_t)(bb * Dn + k) * Hn + h) * Wn + w0 + lane * 4);
            *reinterpret_cast<float4*>(dst) = o;
        }
#pragma unroll
        for (int oj = 0; oj < 4; ++oj) {
            const int djv = 2 * oj - 3;
            const int tt = 9 * (di0 + rr) + djv;
            const int k = (81 - tt) % 81;
            float4 o;
            o.x = acc_o[(rr * 4 + oj) * 4 + 0] * inv;
            o.y = acc_o[(rr * 4 + oj) * 4 + 1] * inv;
            o.z = acc_o[(rr * 4 + oj) * 4 + 2] * inv;
            o.w = acc_o[(rr * 4 + oj) * 4 + 3] * inv;
            float* dst = out + (((size_t)(bb * Dn + k) * Hn + h) * Wn + w0 + lane * 4);
            *reinterpret_cast<float4*>(dst) = o;
        }
    }
}

extern "C" void kernel_launch(void* const* d_in, const int* in_sizes, int n_in,
                              void* d_out, int out_size) {
    const float* x1 = (const float*)d_in[0];
    const float* x2 = (const float*)d_in[1];
    float* out = (float*)d_out;
    dim3 grid(Wn / TWt, Hn / TH, Bn);   // (2, 64, 4) = 512 blocks
    cost_volume_kernel<<<grid, NTHREADS>>>(x1, x2, out);
}